// round 1
// baseline (speedup 1.0000x reference)
#include <cuda_runtime.h>
#include <math.h>

#define LL 10
#define PP 10
#define NEG 50
#define BB 61           // 1 + P + N sequences
#define EE 128
#define HH 128
#define GG 384          // 3*H gates

// Device-global scratch (no allocations allowed)
__device__ float g_enc[BB * HH];
__device__ int   g_cnt = 0;

__global__ __launch_bounds__(384, 1)
void node2vec_gru_kernel(const int*   __restrict__ phr,
                         const int*   __restrict__ pos,
                         const int*   __restrict__ neg,
                         const float* __restrict__ u_emb,
                         const float* __restrict__ v_emb,
                         const float* __restrict__ w_ih,
                         const float* __restrict__ w_hh,
                         const float* __restrict__ b_ih,
                         const float* __restrict__ b_hh,
                         const float* __restrict__ h0,
                         float*       __restrict__ out)
{
    __shared__ __align__(16) float sh_x [LL * EE];   // gathered inputs
    __shared__ __align__(16) float sh_gi[LL * GG];   // input-gate preacts
    __shared__ __align__(16) float sh_h [HH];        // hidden state
    __shared__ float sh_gh[GG];                      // hidden-gate preacts (per step)
    __shared__ float sh_s [64];                      // dot products for loss
    __shared__ int   sh_last;

    const int tid = threadIdx.x;
    const int b   = blockIdx.x;

    // ---- gather x[t][:] for this sequence ----
    for (int idx = tid; idx < LL * EE; idx += 384) {
        const int t = idx >> 7;
        const int j = idx & 127;
        int row;
        const float* emb;
        if (b == 0)        { row = phr[t];                 emb = u_emb; }
        else if (b <= PP)  { row = pos[(b - 1) * LL + t];  emb = v_emb; }
        else               { row = neg[(b - 1 - PP) * LL + t]; emb = v_emb; }
        sh_x[idx] = emb[(long)row * EE + j];
    }
    if (tid < HH) sh_h[tid] = h0[tid];
    __syncthreads();

    // ---- gi[t][g] = b_ih[g] + sum_k x[t][k] * w_ih[g][k] ----
    {
        const int g = tid;
        float acc[LL];
        const float bias = b_ih[g];
        #pragma unroll
        for (int t = 0; t < LL; t++) acc[t] = bias;

        const float4* w4 = reinterpret_cast<const float4*>(w_ih) + g * (EE / 4);
        const float4* x4 = reinterpret_cast<const float4*>(sh_x);
        #pragma unroll 4
        for (int k4 = 0; k4 < EE / 4; k4++) {
            const float4 w = w4[k4];
            #pragma unroll
            for (int t = 0; t < LL; t++) {
                const float4 x = x4[t * (EE / 4) + k4];
                acc[t] += w.x * x.x + w.y * x.y + w.z * x.z + w.w * x.w;
            }
        }
        #pragma unroll
        for (int t = 0; t < LL; t++) sh_gi[t * GG + g] = acc[t];
    }

    // ---- preload this thread's w_hh row into registers ----
    float4 wr[EE / 4];
    {
        const float4* w4 = reinterpret_cast<const float4*>(w_hh) + tid * (EE / 4);
        #pragma unroll
        for (int k4 = 0; k4 < EE / 4; k4++) wr[k4] = w4[k4];
    }
    const float bhh = b_hh[tid];
    __syncthreads();

    // ---- GRU recurrence over L steps ----
    for (int t = 0; t < LL; t++) {
        float gh = bhh;
        const float4* h4 = reinterpret_cast<const float4*>(sh_h);
        #pragma unroll
        for (int k4 = 0; k4 < EE / 4; k4++) {
            const float4 h = h4[k4];
            gh += wr[k4].x * h.x + wr[k4].y * h.y + wr[k4].z * h.z + wr[k4].w * h.w;
        }
        sh_gh[tid] = gh;
        __syncthreads();
        if (tid < HH) {
            const float ir  = sh_gi[t * GG + tid];
            const float iz  = sh_gi[t * GG + HH + tid];
            const float in_ = sh_gi[t * GG + 2 * HH + tid];
            const float hr  = sh_gh[tid];
            const float hz  = sh_gh[HH + tid];
            const float hn  = sh_gh[2 * HH + tid];
            const float r = 1.f / (1.f + expf(-(ir + hr)));
            const float z = 1.f / (1.f + expf(-(iz + hz)));
            const float n = tanhf(in_ + r * hn);
            sh_h[tid] = (1.f - z) * n + z * sh_h[tid];
        }
        __syncthreads();
    }

    // ---- publish final hidden state ----
    if (tid < HH) g_enc[b * HH + tid] = sh_h[tid];
    __threadfence();
    __syncthreads();
    if (tid == 0) {
        const int c = atomicAdd(&g_cnt, 1);
        sh_last = (c == BB - 1) ? 1 : 0;
    }
    __syncthreads();
    if (!sh_last) return;
    __threadfence();   // order g_enc reads after observing all arrivals

    // ---- loss epilogue (last block only) ----
    const int wid  = tid >> 5;
    const int lane = tid & 31;
    for (int i = 1 + wid; i < BB; i += 12) {
        float p = 0.f;
        #pragma unroll
        for (int c = 0; c < 4; c++) {
            const int k = lane + 32 * c;
            p += g_enc[k] * g_enc[i * HH + k];
        }
        #pragma unroll
        for (int off = 16; off; off >>= 1)
            p += __shfl_xor_sync(0xffffffffu, p, off);
        if (lane == 0) sh_s[i] = p * (1.0f / (float)HH);
    }
    __syncthreads();
    if (tid == 0) {
        float pos_loss = 0.f;
        for (int i = 1; i <= PP; i++) pos_loss += sh_s[i];
        float neg_sum = 0.f;
        for (int i = PP + 1; i < BB; i++) {
            const float s = sh_s[i];
            if (s > 0.f) neg_sum += expf(s);
        }
        out[0] = logf(1.f + neg_sum) - pos_loss;
        g_cnt = 0;   // reset for next graph replay
    }
}

extern "C" void kernel_launch(void* const* d_in, const int* in_sizes, int n_in,
                              void* d_out, int out_size)
{
    const int*   phr   = (const int*)  d_in[0];
    const int*   pos   = (const int*)  d_in[1];
    const int*   neg   = (const int*)  d_in[2];
    const float* u_emb = (const float*)d_in[3];
    const float* v_emb = (const float*)d_in[4];
    const float* w_ih  = (const float*)d_in[5];
    const float* w_hh  = (const float*)d_in[6];
    const float* b_ih  = (const float*)d_in[7];
    const float* b_hh  = (const float*)d_in[8];
    const float* h0    = (const float*)d_in[9];
    float* out = (float*)d_out;

    node2vec_gru_kernel<<<BB, 384>>>(phr, pos, neg, u_emb, v_emb,
                                     w_ih, w_hh, b_ih, b_hh, h0, out);
}

// round 2
// speedup vs baseline: 1.1172x; 1.1172x over previous
#include <cuda_runtime.h>
#include <math.h>

#define LL 10
#define PP 10
#define BB 61           // 1 + P + N sequences
#define EE 128
#define HH 128
#define GG 384          // 3*H gates

typedef unsigned long long u64;

// Device-global scratch (no allocations allowed)
__device__ float g_enc[BB * HH];
__device__ int   g_cnt = 0;

__device__ __forceinline__ u64 ffma2(u64 a, u64 b, u64 c) {
    u64 d;
    asm("fma.rn.f32x2 %0, %1, %2, %3;" : "=l"(d) : "l"(a), "l"(b), "l"(c));
    return d;
}
__device__ __forceinline__ float lo32(u64 v) { return __uint_as_float((unsigned)v); }
__device__ __forceinline__ float hi32(u64 v) { return __uint_as_float((unsigned)(v >> 32)); }

__global__ __launch_bounds__(384, 1)
void node2vec_gru_kernel(const int*   __restrict__ phr,
                         const int*   __restrict__ pos,
                         const int*   __restrict__ neg,
                         const float* __restrict__ u_emb,
                         const float* __restrict__ v_emb,
                         const float* __restrict__ w_ih,
                         const float* __restrict__ w_hh,
                         const float* __restrict__ b_ih,
                         const float* __restrict__ b_hh,
                         const float* __restrict__ h0,
                         float*       __restrict__ out)
{
    __shared__ __align__(16) float sh_x [LL * EE];   // gathered inputs
    __shared__ __align__(16) float sh_gi[LL * GG];   // input-gate preacts
    __shared__ __align__(16) float sh_h [HH];        // hidden state
    __shared__ __align__(16) float sh_gh[GG];        // hidden-gate preacts (per step)
    __shared__ float sh_s [64];                      // dot products for loss
    __shared__ int   sh_last;

    const int tid = threadIdx.x;
    const int b   = blockIdx.x;

    // ---- one-shot vectorized gather: 320 float4 = 10 rows x 128 floats ----
    if (tid < 320) {
        const int t  = tid >> 5;
        const int j4 = tid & 31;
        long row;
        const float* emb;
        if (b == 0)        { row = phr[t];                  emb = u_emb; }
        else if (b <= PP)  { row = pos[(b - 1) * LL + t];   emb = v_emb; }
        else               { row = neg[(b - 1 - PP) * LL + t]; emb = v_emb; }
        reinterpret_cast<float4*>(sh_x)[tid] =
            reinterpret_cast<const float4*>(emb)[row * 32 + j4];
    }
    if (tid < HH) sh_h[tid] = h0[tid];
    const float bias = b_ih[tid];
    const float bhh  = b_hh[tid];
    __syncthreads();

    // ---- gi[t][g] = b_ih[g] + sum_k x[t][k] * w_ih[g][k]  (packed f32x2) ----
    {
        const ulonglong2* w2 = reinterpret_cast<const ulonglong2*>(w_ih) + tid * 32;
        const ulonglong2* x2 = reinterpret_cast<const ulonglong2*>(sh_x);
        u64 acc[LL];
        #pragma unroll
        for (int t = 0; t < LL; t++) acc[t] = (u64)__float_as_uint(bias);  // (bias, 0)

        #pragma unroll 8
        for (int k = 0; k < 32; k++) {
            const ulonglong2 w = w2[k];
            #pragma unroll
            for (int t = 0; t < LL; t++) {
                const ulonglong2 x = x2[t * 32 + k];   // uniform-address broadcast
                acc[t] = ffma2(w.x, x.x, acc[t]);
                acc[t] = ffma2(w.y, x.y, acc[t]);
            }
        }
        #pragma unroll
        for (int t = 0; t < LL; t++)
            sh_gi[t * GG + tid] = lo32(acc[t]) + hi32(acc[t]);
    }

    // ---- preload this thread's w_hh row into registers (as f32x2 pairs) ----
    u64 wr[64];
    {
        const ulonglong2* wh2 = reinterpret_cast<const ulonglong2*>(w_hh) + tid * 32;
        #pragma unroll
        for (int k = 0; k < 32; k++) {
            const ulonglong2 v = wh2[k];
            wr[2 * k]     = v.x;
            wr[2 * k + 1] = v.y;
        }
    }
    __syncthreads();

    // ---- GRU recurrence over L steps ----
    for (int t = 0; t < LL; t++) {
        // gh = b_hh + dot(w_hh_row, h): packed FMA, 4 independent chains
        u64 a0 = 0ull, a1 = 0ull, a2 = 0ull, a3 = 0ull;
        const ulonglong2* h2 = reinterpret_cast<const ulonglong2*>(sh_h);
        #pragma unroll
        for (int k = 0; k < 32; k++) {
            const ulonglong2 hv = h2[k];               // broadcast
            if (k & 1) {
                a2 = ffma2(wr[2 * k],     hv.x, a2);
                a3 = ffma2(wr[2 * k + 1], hv.y, a3);
            } else {
                a0 = ffma2(wr[2 * k],     hv.x, a0);
                a1 = ffma2(wr[2 * k + 1], hv.y, a1);
            }
        }
        const float gh = bhh + ((lo32(a0) + hi32(a0)) + (lo32(a1) + hi32(a1)))
                             + ((lo32(a2) + hi32(a2)) + (lo32(a3) + hi32(a3)));
        sh_gh[tid] = gh;
        __syncthreads();
        if (tid < HH) {
            const float ir  = sh_gi[t * GG + tid];
            const float iz  = sh_gi[t * GG + HH + tid];
            const float in_ = sh_gi[t * GG + 2 * HH + tid];
            const float hr  = sh_gh[tid];
            const float hz  = sh_gh[HH + tid];
            const float hn  = sh_gh[2 * HH + tid];
            const float r = __fdividef(1.f, 1.f + __expf(-(ir + hr)));
            const float z = __fdividef(1.f, 1.f + __expf(-(iz + hz)));
            const float n = tanhf(in_ + r * hn);
            sh_h[tid] = (1.f - z) * n + z * sh_h[tid];
        }
        __syncthreads();
    }

    // ---- publish final hidden state ----
    if (tid < HH) g_enc[b * HH + tid] = sh_h[tid];
    __threadfence();
    __syncthreads();
    if (tid == 0) {
        const int c = atomicAdd(&g_cnt, 1);
        sh_last = (c == BB - 1) ? 1 : 0;
    }
    __syncthreads();
    if (!sh_last) return;
    __threadfence();   // order g_enc reads after observing all arrivals

    // ---- loss epilogue (last block only) ----
    const int wid  = tid >> 5;
    const int lane = tid & 31;
    for (int i = 1 + wid; i < BB; i += 12) {
        float p = 0.f;
        #pragma unroll
        for (int c = 0; c < 4; c++) {
            const int k = lane + 32 * c;
            p += g_enc[k] * g_enc[i * HH + k];
        }
        #pragma unroll
        for (int off = 16; off; off >>= 1)
            p += __shfl_xor_sync(0xffffffffu, p, off);
        if (lane == 0) sh_s[i] = p * (1.0f / (float)HH);
    }
    __syncthreads();
    if (tid == 0) {
        float pos_loss = 0.f;
        #pragma unroll
        for (int i = 1; i <= PP; i++) pos_loss += sh_s[i];
        float neg_sum = 0.f;
        #pragma unroll
        for (int i = PP + 1; i < BB; i++) {
            const float s = sh_s[i];
            if (s > 0.f) neg_sum += __expf(s);
        }
        out[0] = logf(1.f + neg_sum) - pos_loss;
        g_cnt = 0;   // reset for next graph replay
    }
}

extern "C" void kernel_launch(void* const* d_in, const int* in_sizes, int n_in,
                              void* d_out, int out_size)
{
    const int*   phr   = (const int*)  d_in[0];
    const int*   pos   = (const int*)  d_in[1];
    const int*   neg   = (const int*)  d_in[2];
    const float* u_emb = (const float*)d_in[3];
    const float* v_emb = (const float*)d_in[4];
    const float* w_ih  = (const float*)d_in[5];
    const float* w_hh  = (const float*)d_in[6];
    const float* b_ih  = (const float*)d_in[7];
    const float* b_hh  = (const float*)d_in[8];
    const float* h0    = (const float*)d_in[9];
    float* out = (float*)d_out;

    node2vec_gru_kernel<<<BB, 384>>>(phr, pos, neg, u_emb, v_emb,
                                     w_ih, w_hh, b_ih, b_hh, h0, out);
}

// round 3
// speedup vs baseline: 1.3842x; 1.2389x over previous
#include <cuda_runtime.h>
#include <math.h>

#define LL 10
#define PP 10
#define BB 61           // 1 + P + N sequences
#define EE 128
#define HH 128
#define GG 384          // 3*H gates

#define ROWF 132        // padded row stride in floats (528B: conflict-free)
#define ROW16 33        // padded row stride in 16B units

typedef unsigned long long u64;

// smem layout (bytes)
#define OFF_W    0
#define W_BYTES  (GG * ROWF * 4)          /* 202752 */
#define OFF_X    (OFF_W + W_BYTES)        /* 202752 */
#define OFF_GI   (OFF_X + LL * EE * 4)    /* 207872 */
#define OFF_GH   (OFF_GI + LL * GG * 4)   /* 223232 */
#define OFF_H    (OFF_GH + GG * 4)        /* 224768 */
#define OFF_S    (OFF_H + HH * 4)         /* 225280 */
#define OFF_LAST (OFF_S + 64 * 4)         /* 225536 */
#define SMEM_TOTAL (OFF_LAST + 16)        /* 225552 */

// Device-global scratch (no allocations allowed)
__device__ float g_enc[BB * HH];
__device__ int   g_cnt = 0;

__device__ __forceinline__ u64 ffma2(u64 a, u64 b, u64 c) {
    u64 d;
    asm("fma.rn.f32x2 %0, %1, %2, %3;" : "=l"(d) : "l"(a), "l"(b), "l"(c));
    return d;
}
__device__ __forceinline__ float lo32(u64 v) { return __uint_as_float((unsigned)v); }
__device__ __forceinline__ float hi32(u64 v) { return __uint_as_float((unsigned)(v >> 32)); }

// Coalesced stage of a 384x128 f32 row-major matrix into padded smem.
// Warp w handles rows 32w..32w+31; one LDG.128 + one STS.128 per row.
__device__ __forceinline__ void stage_weights(float4* dst4, const float4* src4,
                                              int wid, int lane)
{
    const int row_base = wid * 32;
    #pragma unroll 8
    for (int i = 0; i < 32; i++) {
        const int row = row_base + i;
        dst4[row * ROW16 + lane] = src4[row * 32 + lane];   // coalesced LDG / conflict-free STS
    }
}

__global__ __launch_bounds__(384, 1)
void node2vec_gru_kernel(const int*   __restrict__ phr,
                         const int*   __restrict__ pos,
                         const int*   __restrict__ neg,
                         const float* __restrict__ u_emb,
                         const float* __restrict__ v_emb,
                         const float* __restrict__ w_ih,
                         const float* __restrict__ w_hh,
                         const float* __restrict__ b_ih,
                         const float* __restrict__ b_hh,
                         const float* __restrict__ h0,
                         float*       __restrict__ out)
{
    extern __shared__ __align__(16) char smem[];
    float4* Wbuf4 = reinterpret_cast<float4*>(smem + OFF_W);
    float*  sh_x  = reinterpret_cast<float*>(smem + OFF_X);
    float*  sh_gi = reinterpret_cast<float*>(smem + OFF_GI);
    float*  sh_gh = reinterpret_cast<float*>(smem + OFF_GH);
    float*  sh_h  = reinterpret_cast<float*>(smem + OFF_H);
    float*  sh_s  = reinterpret_cast<float*>(smem + OFF_S);
    int*    sh_last = reinterpret_cast<int*>(smem + OFF_LAST);

    const int tid  = threadIdx.x;
    const int wid  = tid >> 5;
    const int lane = tid & 31;
    const int b    = blockIdx.x;

    // ---- stage w_ih into padded smem (coalesced) ----
    stage_weights(Wbuf4, reinterpret_cast<const float4*>(w_ih), wid, lane);

    // ---- one-shot vectorized gather: warp t loads row t (coalesced) ----
    if (tid < 320) {
        const int t  = wid;          // warps 0..9
        long row;
        const float* emb;
        if (b == 0)        { row = phr[t];                  emb = u_emb; }
        else if (b <= PP)  { row = pos[(b - 1) * LL + t];   emb = v_emb; }
        else               { row = neg[(b - 1 - PP) * LL + t]; emb = v_emb; }
        reinterpret_cast<float4*>(sh_x)[t * 32 + lane] =
            reinterpret_cast<const float4*>(emb)[row * 32 + lane];
    }
    if (tid < HH) sh_h[tid] = h0[tid];
    const float bias = b_ih[tid];
    const float bhh  = b_hh[tid];
    __syncthreads();

    // ---- gi[t][g] = b_ih[g] + dot(w_ih[g], x[t]) ----
    // w from padded smem (conflict-free per-thread row), x broadcast.
    {
        const ulonglong2* Wrow = reinterpret_cast<const ulonglong2*>(smem + OFF_W)
                                 + tid * ROW16;
        const ulonglong2* X2   = reinterpret_cast<const ulonglong2*>(sh_x);
        u64 acc[LL];
        #pragma unroll
        for (int t = 0; t < LL; t++) acc[t] = (u64)__float_as_uint(bias);  // (bias, 0)

        #pragma unroll 8
        for (int k = 0; k < 32; k++) {
            const ulonglong2 w = Wrow[k];
            #pragma unroll
            for (int t = 0; t < LL; t++) {
                const ulonglong2 x = X2[t * 32 + k];   // uniform-address broadcast
                acc[t] = ffma2(w.x, x.x, acc[t]);
                acc[t] = ffma2(w.y, x.y, acc[t]);
            }
        }
        #pragma unroll
        for (int t = 0; t < LL; t++)
            sh_gi[t * GG + tid] = lo32(acc[t]) + hi32(acc[t]);
    }
    __syncthreads();   // all gi reads of Wbuf done

    // ---- stage w_hh into the same padded buffer (coalesced) ----
    stage_weights(Wbuf4, reinterpret_cast<const float4*>(w_hh), wid, lane);
    __syncthreads();

    // ---- preload this thread's padded w_hh row into registers (conflict-free) ----
    u64 wr[64];
    {
        const ulonglong2* Wrow = reinterpret_cast<const ulonglong2*>(smem + OFF_W)
                                 + tid * ROW16;
        #pragma unroll
        for (int k = 0; k < 32; k++) {
            const ulonglong2 v = Wrow[k];
            wr[2 * k]     = v.x;
            wr[2 * k + 1] = v.y;
        }
    }

    // ---- GRU recurrence over L steps ----
    for (int t = 0; t < LL; t++) {
        u64 a0 = 0ull, a1 = 0ull, a2 = 0ull, a3 = 0ull;
        const ulonglong2* H2 = reinterpret_cast<const ulonglong2*>(sh_h);
        #pragma unroll
        for (int k = 0; k < 32; k++) {
            const ulonglong2 hv = H2[k];               // broadcast
            if (k & 1) {
                a2 = ffma2(wr[2 * k],     hv.x, a2);
                a3 = ffma2(wr[2 * k + 1], hv.y, a3);
            } else {
                a0 = ffma2(wr[2 * k],     hv.x, a0);
                a1 = ffma2(wr[2 * k + 1], hv.y, a1);
            }
        }
        const float gh = bhh + ((lo32(a0) + hi32(a0)) + (lo32(a1) + hi32(a1)))
                             + ((lo32(a2) + hi32(a2)) + (lo32(a3) + hi32(a3)));
        sh_gh[tid] = gh;
        __syncthreads();
        if (tid < HH) {
            const float ir  = sh_gi[t * GG + tid];
            const float iz  = sh_gi[t * GG + HH + tid];
            const float in_ = sh_gi[t * GG + 2 * HH + tid];
            const float hr  = sh_gh[tid];
            const float hz  = sh_gh[HH + tid];
            const float hn  = sh_gh[2 * HH + tid];
            const float r = __fdividef(1.f, 1.f + __expf(-(ir + hr)));
            const float z = __fdividef(1.f, 1.f + __expf(-(iz + hz)));
            const float n = tanhf(in_ + r * hn);
            sh_h[tid] = (1.f - z) * n + z * sh_h[tid];
        }
        __syncthreads();
    }

    // ---- publish final hidden state ----
    if (tid < HH) g_enc[b * HH + tid] = sh_h[tid];
    __threadfence();
    __syncthreads();
    if (tid == 0) {
        const int c = atomicAdd(&g_cnt, 1);
        *sh_last = (c == BB - 1) ? 1 : 0;
    }
    __syncthreads();
    if (!*sh_last) return;
    __threadfence();   // order g_enc reads after observing all arrivals

    // ---- loss epilogue (last block only) ----
    for (int i = 1 + wid; i < BB; i += 12) {
        float p = 0.f;
        #pragma unroll
        for (int c = 0; c < 4; c++) {
            const int k = lane + 32 * c;
            p += g_enc[k] * g_enc[i * HH + k];
        }
        #pragma unroll
        for (int off = 16; off; off >>= 1)
            p += __shfl_xor_sync(0xffffffffu, p, off);
        if (lane == 0) sh_s[i] = p * (1.0f / (float)HH);
    }
    __syncthreads();
    if (tid == 0) {
        float pos_loss = 0.f;
        #pragma unroll
        for (int i = 1; i <= PP; i++) pos_loss += sh_s[i];
        float neg_sum = 0.f;
        #pragma unroll
        for (int i = PP + 1; i < BB; i++) {
            const float s = sh_s[i];
            if (s > 0.f) neg_sum += __expf(s);
        }
        out[0] = logf(1.f + neg_sum) - pos_loss;
        g_cnt = 0;   // reset for next graph replay
    }
}

extern "C" void kernel_launch(void* const* d_in, const int* in_sizes, int n_in,
                              void* d_out, int out_size)
{
    const int*   phr   = (const int*)  d_in[0];
    const int*   pos   = (const int*)  d_in[1];
    const int*   neg   = (const int*)  d_in[2];
    const float* u_emb = (const float*)d_in[3];
    const float* v_emb = (const float*)d_in[4];
    const float* w_ih  = (const float*)d_in[5];
    const float* w_hh  = (const float*)d_in[6];
    const float* b_ih  = (const float*)d_in[7];
    const float* b_hh  = (const float*)d_in[8];
    const float* h0    = (const float*)d_in[9];
    float* out = (float*)d_out;

    cudaFuncSetAttribute(node2vec_gru_kernel,
                         cudaFuncAttributeMaxDynamicSharedMemorySize, SMEM_TOTAL);
    node2vec_gru_kernel<<<BB, 384, SMEM_TOTAL>>>(phr, pos, neg, u_emb, v_emb,
                                                 w_ih, w_hh, b_ih, b_hh, h0, out);
}